// round 2
// baseline (speedup 1.0000x reference)
#include <cuda_runtime.h>
#include <cstdint>

// ============================================================================
// Problem constants
// ============================================================================
#define M_DIM 4096
#define K_DIM 4096
#define S_DIM 2048
#define N_DIM 16384            // B*S = 8*2048

#define BM 128
#define BN 256
#define BK 32
#define K_ITERS (K_DIM / BK)   // 128
#define STAGES 3

#define THREADS 512            // 16 warps: 4 (m) x 4 (n)
// warp tile: 32 (m) x 64 (n); per-warp mma grid: 2 x 8 of m16n8k8

// SMEM: padded row stride 36 floats (144B, 16B-aligned, conflict-free frags)
#define SKA 36
#define A_STAGE_ELEMS (BM * SKA)              // 4608
#define B_STAGE_ELEMS (BN * SKA)              // 9216
#define STAGE_ELEMS   (A_STAGE_ELEMS + B_STAGE_ELEMS)   // 13824
#define SMEM_BYTES    (STAGES * STAGE_ELEMS * 4)        // 165888

// ============================================================================
// Scratch (device globals — no runtime allocation allowed)
// ============================================================================
__device__ __align__(128) float g_W[(size_t)M_DIM * K_DIM];   // 64 MB densified W (tf32-rounded)
__device__ __align__(128) float g_X[(size_t)N_DIM * K_DIM];   // 256 MB tf32-rounded x

// ============================================================================
// Helpers
// ============================================================================
__device__ __forceinline__ float tf32_rna(float f) {
    float o;
    asm("cvt.rna.tf32.f32 %0, %1;" : "=f"(o) : "f"(f));
    return o;
}

__device__ __forceinline__ uint32_t smem_u32(const void* p) {
    uint32_t a;
    asm("{ .reg .u64 t; cvta.to.shared.u64 t, %1; cvt.u32.u64 %0, t; }"
        : "=r"(a) : "l"(p));
    return a;
}

__device__ __forceinline__ void cp_async16(uint32_t dst, const void* src) {
    asm volatile("cp.async.cg.shared.global [%0], [%1], 16;"
                 :: "r"(dst), "l"(src));
}
__device__ __forceinline__ void cp_commit() {
    asm volatile("cp.async.commit_group;");
}
__device__ __forceinline__ void cp_wait1() {
    asm volatile("cp.async.wait_group 1;");
}

__device__ __forceinline__ void mma_tf32(float* c, const uint32_t* a,
                                         uint32_t b0, uint32_t b1) {
    asm volatile(
        "mma.sync.aligned.m16n8k8.row.col.f32.tf32.tf32.f32 "
        "{%0,%1,%2,%3}, {%4,%5,%6,%7}, {%8,%9}, {%0,%1,%2,%3};"
        : "+f"(c[0]), "+f"(c[1]), "+f"(c[2]), "+f"(c[3])
        : "r"(a[0]), "r"(a[1]), "r"(a[2]), "r"(a[3]), "r"(b0), "r"(b1));
}

// ============================================================================
// Pre-pass kernels
// ============================================================================
__global__ void scatter_kernel(const float* __restrict__ vals,
                               const int* __restrict__ rows,
                               const int* __restrict__ cols, int nnz) {
    int i = blockIdx.x * blockDim.x + threadIdx.x;
    if (i < nnz) {
        atomicAdd(&g_W[(size_t)rows[i] * K_DIM + cols[i]], vals[i]);
    }
}

__global__ void round_w_kernel() {
    size_t n4 = (size_t)M_DIM * K_DIM / 4;
    float4* p = reinterpret_cast<float4*>(g_W);
    for (size_t i = blockIdx.x * blockDim.x + threadIdx.x; i < n4;
         i += (size_t)gridDim.x * blockDim.x) {
        float4 v = p[i];
        v.x = tf32_rna(v.x); v.y = tf32_rna(v.y);
        v.z = tf32_rna(v.z); v.w = tf32_rna(v.w);
        p[i] = v;
    }
}

__global__ void conv_x_kernel(const float* __restrict__ x) {
    size_t n4 = (size_t)N_DIM * K_DIM / 4;
    const float4* src = reinterpret_cast<const float4*>(x);
    float4* dst = reinterpret_cast<float4*>(g_X);
    for (size_t i = blockIdx.x * blockDim.x + threadIdx.x; i < n4;
         i += (size_t)gridDim.x * blockDim.x) {
        float4 v = src[i];
        v.x = tf32_rna(v.x); v.y = tf32_rna(v.y);
        v.z = tf32_rna(v.z); v.w = tf32_rna(v.w);
        dst[i] = v;
    }
}

// ============================================================================
// tf32 mma.sync GEMM: out[b,m,s] = sum_k W[m,k] * X[n,k] + bias[s],  n=b*2048+s
// ============================================================================
__global__ void __launch_bounds__(THREADS, 1) gemm_kernel(
    const float* __restrict__ bias, float* __restrict__ out)
{
    extern __shared__ uint32_t smem[];
    const uint32_t sbase = smem_u32(smem);

    const int tid  = threadIdx.x;
    const int wid  = tid >> 5;
    const int lane = tid & 31;
    const int g = lane >> 2;        // fragment row group 0..7
    const int t = lane & 3;         // fragment col group 0..3
    const int wm = wid & 3;         // warp m index 0..3
    const int wn = wid >> 2;        // warp n index 0..3

    // CTA tile mapping: bid = mt + 32*nt so a wave covers all m-tiles (A reuse)
    const int mt = blockIdx.x & 31;
    const int nt = blockIdx.x >> 5;
    const int m0 = mt * BM;
    const int n0 = nt * BN;

    // per-thread cp.async assignments: chunk = 16B
    // A: 128 rows x 8 chunks = 1024 -> 2/thread; B: 256 x 8 = 2048 -> 4/thread
    int a_row[2], a_seg[2];
    int b_row[4], b_seg[4];
#pragma unroll
    for (int i = 0; i < 2; i++) {
        int c = tid + i * THREADS;
        a_row[i] = c >> 3; a_seg[i] = c & 7;
    }
#pragma unroll
    for (int i = 0; i < 4; i++) {
        int c = tid + i * THREADS;
        b_row[i] = c >> 3; b_seg[i] = c & 7;
    }

    const float* Abase = g_W + (size_t)m0 * K_DIM;
    const float* Bbase = g_X + (size_t)n0 * K_DIM;

    auto load_stage = [&](int stage, int ks) {
        uint32_t so = sbase + (uint32_t)(stage * STAGE_ELEMS) * 4u;
#pragma unroll
        for (int i = 0; i < 2; i++) {
            cp_async16(so + (uint32_t)(a_row[i] * SKA + a_seg[i] * 4) * 4u,
                       Abase + (size_t)a_row[i] * K_DIM + ks * BK + a_seg[i] * 4);
        }
#pragma unroll
        for (int i = 0; i < 4; i++) {
            cp_async16(so + (uint32_t)(A_STAGE_ELEMS + b_row[i] * SKA + b_seg[i] * 4) * 4u,
                       Bbase + (size_t)b_row[i] * K_DIM + ks * BK + b_seg[i] * 4);
        }
    };

    float acc[2][8][4];
#pragma unroll
    for (int i = 0; i < 2; i++)
#pragma unroll
        for (int j = 0; j < 8; j++)
#pragma unroll
            for (int r = 0; r < 4; r++) acc[i][j][r] = 0.0f;

    // prologue: fill STAGES-1 stages
    load_stage(0, 0); cp_commit();
    load_stage(1, 1); cp_commit();

    for (int k = 0; k < K_ITERS; k++) {
        cp_wait1();
        __syncthreads();

        // prefetch next stage (overwrites the stage computed last iteration,
        // protected by the __syncthreads above)
        if (k + 2 < K_ITERS) load_stage((k + 2) % STAGES, k + 2);
        cp_commit();

        const int st = k % STAGES;
        const uint32_t* sA = smem + st * STAGE_ELEMS;
        const uint32_t* sB = sA + A_STAGE_ELEMS;

#pragma unroll
        for (int kk = 0; kk < 4; kk++) {
            uint32_t a[2][4];
#pragma unroll
            for (int mi = 0; mi < 2; mi++) {
                int r0 = wm * 32 + mi * 16 + g;
                int cbase = kk * 8 + t;
                a[mi][0] = sA[r0 * SKA + cbase];
                a[mi][1] = sA[(r0 + 8) * SKA + cbase];
                a[mi][2] = sA[r0 * SKA + cbase + 4];
                a[mi][3] = sA[(r0 + 8) * SKA + cbase + 4];
            }
#pragma unroll
            for (int ni = 0; ni < 8; ni++) {
                int nr = wn * 64 + ni * 8 + g;
                int cbase = kk * 8 + t;
                uint32_t b0 = sB[nr * SKA + cbase];
                uint32_t b1 = sB[nr * SKA + cbase + 4];
                mma_tf32(acc[0][ni], a[0], b0, b1);
                mma_tf32(acc[1][ni], a[1], b0, b1);
            }
        }
    }

    // ------------------------------------------------------------------------
    // Epilogue: out[b, m, s] = acc + bias[s]; whole CTA tile is in one batch
    // ------------------------------------------------------------------------
    const int b   = n0 >> 11;        // n0 / 2048
    const int s0c = n0 & 2047;
    float* obase = out + (size_t)b * M_DIM * S_DIM;

#pragma unroll
    for (int mi = 0; mi < 2; mi++) {
#pragma unroll
        for (int ni = 0; ni < 8; ni++) {
            int sl = s0c + wn * 64 + ni * 8 + 2 * t;
            float2 bv = *reinterpret_cast<const float2*>(bias + sl);
            int m = m0 + wm * 32 + mi * 16 + g;

            float2 v0;
            v0.x = acc[mi][ni][0] + bv.x;
            v0.y = acc[mi][ni][1] + bv.y;
            *reinterpret_cast<float2*>(obase + (size_t)m * S_DIM + sl) = v0;

            float2 v1;
            v1.x = acc[mi][ni][2] + bv.x;
            v1.y = acc[mi][ni][3] + bv.y;
            *reinterpret_cast<float2*>(obase + (size_t)(m + 8) * S_DIM + sl) = v1;
        }
    }
}

// ============================================================================
// Host launch
// ============================================================================
extern "C" void kernel_launch(void* const* d_in, const int* in_sizes, int n_in,
                              void* d_out, int out_size) {
    const float* x      = (const float*)d_in[0];
    const float* values = (const float*)d_in[1];
    const float* bias   = (const float*)d_in[2];
    const int* row_ids  = (const int*)d_in[3];
    const int* col_idx  = (const int*)d_in[4];
    int nnz = in_sizes[1];
    float* out = (float*)d_out;

    void* wptr = nullptr;
    cudaGetSymbolAddress(&wptr, g_W);

    // 1) zero W (each replay re-accumulates from zero)
    cudaMemsetAsync(wptr, 0, (size_t)M_DIM * K_DIM * sizeof(float));

    // 2) scatter-add COO values into dense W
    scatter_kernel<<<(nnz + 255) / 256, 256>>>(values, row_ids, col_idx, nnz);

    // 3) round W in place and copy+round x to tf32 (RN-to-nearest-away) so the
    //    HMMA tf32 truncation is exact
    round_w_kernel<<<4096, 256>>>();
    conv_x_kernel<<<8192, 256>>>(x);

    // 4) GEMM
    static bool attr_set = false;
    if (!attr_set) {
        cudaFuncSetAttribute(gemm_kernel,
                             cudaFuncAttributeMaxDynamicSharedMemorySize,
                             SMEM_BYTES);
        attr_set = true;
    }
    gemm_kernel<<<(M_DIM / BM) * (N_DIM / BN), THREADS, SMEM_BYTES>>>(bias, out);
}